// round 9
// baseline (speedup 1.0000x reference)
#include <cuda_runtime.h>

#define BB 64
#define HH 56
#define WW 56
#define CC 256
#define COUT 64
#define ROUTES 4
#define RW (CC / ROUTES)          // 64 channels per route
#define RCHUNKS 14                // 4 rows per chunk
#define SLOTS 9                   // 3x3 (dh,dw) classes
#define NPATCH (BB * RCHUNKS)     // 896 patch blocks
#define GTILES 49                 // 64-pixel gather tiles per batch
#define NGATHER (BB * GTILES)     // 3136 gather blocks

// per-(batch,chunk) partial patch sums: [BB][RCHUNKS][SLOTS][CC] floats (~8 MB)
__device__ float g_S2[BB * RCHUNKS * SLOTS * CC];
__device__ int   g_cnt[BB];       // patch completion counters (self-resetting)
__device__ int   g_gcnt[BB];      // gather completion counters (self-resetting)
__device__ volatile int g_ready[BB];  // route-ready flags (self-resetting)
__device__ int   g_route[BB];

__device__ __forceinline__ float4 f4add(float4 a, float4 b) {
    return make_float4(a.x + b.x, a.y + b.y, a.z + b.z, a.w + b.w);
}
__device__ __forceinline__ float4 f4sub(float4 a, float4 b) {
    return make_float4(a.x - b.x, a.y - b.y, a.z - b.z, a.w - b.w);
}

// ---------------------------------------------------------------------------
// Mega-kernel: ONE launch.
//   bid in [0, 896):    patch-sum block (b = bid/14 -> batch-contiguous, so
//                       early batches complete early). Last block per batch
//                       (atomic counter) runs the routing tail and publishes
//                       g_ready[b] (release).
//   bid in [896, 4032): gather block for (b, 64-pixel tile). Spin-waits
//                       (nanosleep backoff) on g_ready[b], then copies the
//                       routed 64-channel group. Dispatch order guarantees
//                       all patch blocks precede gather blocks -> no deadlock.
// All flags/counters self-reset so the CUDA-graph replay is deterministic.
// ---------------------------------------------------------------------------
__global__ __launch_bounds__(256) void routing_mega_kernel(const float* __restrict__ in,
                                                           const float* __restrict__ conv_w,
                                                           const float* __restrict__ conv_b,
                                                           const float* __restrict__ fc_w,
                                                           const float* __restrict__ fc_b,
                                                           float* __restrict__ out_logits,
                                                           float* __restrict__ out_x) {
    const int bid = blockIdx.x;
    const int tid = threadIdx.x;

    if (bid < NPATCH) {
        // ================= PATCH PHASE =================
        const int b     = bid / RCHUNKS;
        const int chunk = bid % RCHUNKS;
        const int q     = tid & 63;            // channel quad 0..63
        const int rt    = tid >> 6;            // row-thread 0..3
        const int h     = chunk * 4 + rt;

        const float4* row = (const float4*)in
                          + ((size_t)(b * HH + h) * WW) * (CC / 4) + q;

        float4 e = make_float4(0.f, 0.f, 0.f, 0.f);
        float4 o = make_float4(0.f, 0.f, 0.f, 0.f);
        float4 v0, v54, v55;
#pragma unroll
        for (int w = 0; w < WW; w += 2) {
            float4 a  = row[(size_t)w * (CC / 4)];
            float4 bb = row[(size_t)(w + 1) * (CC / 4)];
            if (w == 0)  { v0 = a; }
            if (w == 54) { v54 = a; v55 = bb; }
            e = f4add(e, a);
            o = f4add(o, bb);
        }

        __shared__ float4 sacc[4][3][64];
        sacc[rt][0][q] = f4sub(e, v54);  // W0: even w in [0,52]
        sacc[rt][1][q] = f4sub(o, v55);  // W1: odd  w in [1,53]
        sacc[rt][2][q] = f4sub(e, v0);   // W2: even w in [2,54]
        __syncthreads();

        if (rt == 0) {
            float4 outv[SLOTS];
#pragma unroll
            for (int s = 0; s < SLOTS; s++) outv[s] = make_float4(0.f, 0.f, 0.f, 0.f);

#pragma unroll
            for (int r = 0; r < 4; r++) {
                const int hh = chunk * 4 + r;
                const float4 W0 = sacc[r][0][q];
                const float4 W1 = sacc[r][1][q];
                const float4 W2 = sacc[r][2][q];
                if ((hh & 1) == 0) {
                    if (hh <= 52) { outv[0] = f4add(outv[0], W0); outv[1] = f4add(outv[1], W1); outv[2] = f4add(outv[2], W2); }
                    if (hh >= 2)  { outv[6] = f4add(outv[6], W0); outv[7] = f4add(outv[7], W1); outv[8] = f4add(outv[8], W2); }
                } else {
                    if (hh <= 53) { outv[3] = f4add(outv[3], W0); outv[4] = f4add(outv[4], W1); outv[5] = f4add(outv[5], W2); }
                }
            }

            float4* dst = (float4*)g_S2 + ((size_t)(b * RCHUNKS + chunk) * SLOTS) * (CC / 4) + q;
#pragma unroll
            for (int s = 0; s < SLOTS; s++)
                dst[(size_t)s * (CC / 4)] = outv[s];
        }
        __syncthreads();

        // ---- per-batch completion counter; only the last block proceeds ----
        __shared__ int s_last;
        if (tid == 0) {
            __threadfence();                        // publish g_S2 stores
            int old = atomicAdd(&g_cnt[b], 1);
            s_last = (old == RCHUNKS - 1);
            if (s_last) g_cnt[b] = 0;               // reset for next replay
        }
        __syncthreads();
        if (!s_last) return;
        if (tid == 0) __threadfence();              // acquire side
        __syncthreads();

        // ---- tail: sum 14 chunk-partials -> sS(2304) ------------------------
        __shared__ __align__(16) float sS[SLOTS * CC];
        for (int i = tid; i < SLOTS * CC / 4; i += 256) {
            float4 s = make_float4(0.f, 0.f, 0.f, 0.f);
#pragma unroll
            for (int k = 0; k < RCHUNKS; k++) {
                const float4* src = (const float4*)g_S2
                                  + (size_t)(b * RCHUNKS + k) * (SLOTS * CC / 4) + i;
                s = f4add(s, __ldcg(src));
            }
            ((float4*)sS)[i] = s;
        }
        __syncthreads();

        // ---- pooled GEMM: 4 sub-segments of 576 per output ------------------
        const int oc  = tid & 63;
        const int sub = tid >> 6;
        const int j0  = sub * 576;

        float acc = 0.f;
#pragma unroll 8
        for (int j = 0; j < 576; j++)
            acc = fmaf(sS[j0 + j], conv_w[(size_t)(j0 + j) * COUT + oc], acc);

        __shared__ float part[4][COUT];
        part[sub][oc] = acc;
        __syncthreads();

        __shared__ float sp[COUT];
        __shared__ float slog[ROUTES];
        if (tid < COUT) {
            sp[tid] = (part[0][tid] + part[1][tid] + part[2][tid] + part[3][tid])
                      * (1.0f / 729.0f) + conv_b[tid];
        }
        __syncthreads();

        if (tid < ROUTES) {
            float l = fc_b[tid];
#pragma unroll
            for (int j = 0; j < COUT; j++)
                l = fmaf(sp[j], fc_w[j * ROUTES + tid], l);
            slog[tid] = l;
            out_logits[b * ROUTES + tid] = l;
        }
        __syncthreads();

        if (tid == 0) {
            float best = slog[0];
            int br = 0;
#pragma unroll
            for (int r = 1; r < ROUTES; r++)
                if (slog[r] > best) { best = slog[r]; br = r; }  // first-max == argmax
            g_route[b] = br;
            __threadfence();                        // release
            g_ready[b] = 1;
        }
    } else {
        // ================= GATHER PHASE =================
        const int g    = bid - NPATCH;
        const int b    = g / GTILES;
        const int tile = g % GTILES;

        __shared__ int s_route;
        if (tid == 0) {
            while (g_ready[b] == 0) { __nanosleep(128); }
            __threadfence();                        // acquire
            s_route = g_route[b];
        }
        __syncthreads();
        const int r = s_route;

        const size_t base_pix = (size_t)b * (HH * WW) + (size_t)tile * 64;
        const float4* src = (const float4*)in + base_pix * (CC / 4) + r * (RW / 4);
        float4* dst = (float4*)out_x + base_pix * (RW / 4);

#pragma unroll
        for (int k = 0; k < 4; k++) {
            const int item = tid + k * 256;      // 0..1023 = 64 pixels x 16 float4
            const int p = item >> 4;
            const int j = item & 15;
            dst[item] = src[(size_t)p * (CC / 4) + j];
        }
        __syncthreads();

        // last gather block of batch resets the ready flag for the next replay
        if (tid == 0) {
            int old = atomicAdd(&g_gcnt[b], 1);
            if (old == GTILES - 1) {
                g_gcnt[b] = 0;
                g_ready[b] = 0;
            }
        }
    }
}

// ---------------------------------------------------------------------------
extern "C" void kernel_launch(void* const* d_in, const int* in_sizes, int n_in,
                              void* d_out, int out_size) {
    const float* in     = (const float*)d_in[0];
    const float* conv_w = (const float*)d_in[1];
    const float* conv_b = (const float*)d_in[2];
    const float* fc_w   = (const float*)d_in[3];
    const float* fc_b   = (const float*)d_in[4];

    float* out        = (float*)d_out;
    float* out_logits = out + (size_t)BB * HH * WW * RW;  // x first, then logits

    routing_mega_kernel<<<NPATCH + NGATHER, 256>>>(in, conv_w, conv_b, fc_w, fc_b,
                                                   out_logits, out);
}